// round 3
// baseline (speedup 1.0000x reference)
#include <cuda_runtime.h>
#include <cuda_bf16.h>
#include <stdint.h>

#define BT     16384   // B*T
#define C_DIM  1024
#define HD     1024    // N_HEAD * HEAD_SIZE
#define RANK   128
#define TT     256     // T
#define NH     16
#define HS     64

typedef __nv_bfloat16 bf16;

// ---------------- scratch (device globals; no allocation allowed) ----------
__device__ bf16  g_x_hi[(size_t)BT * C_DIM];
__device__ bf16  g_x_lo[(size_t)BT * C_DIM];
__device__ bf16  g_wq_hi[(size_t)HD * C_DIM];      // [N][K] transposed
__device__ bf16  g_wq_lo[(size_t)HD * C_DIM];
__device__ bf16  g_wkvd_hi[(size_t)RANK * C_DIM];
__device__ bf16  g_wkvd_lo[(size_t)RANK * C_DIM];
__device__ bf16  g_wkvu_hi[(size_t)2 * HD * RANK];
__device__ bf16  g_wkvu_lo[(size_t)2 * HD * RANK];
__device__ bf16  g_wo_hi[(size_t)C_DIM * HD];
__device__ bf16  g_wo_lo[(size_t)C_DIM * HD];
__device__ float g_q[(size_t)BT * HD];
__device__ bf16  g_lat_hi[(size_t)BT * RANK];
__device__ bf16  g_lat_lo[(size_t)BT * RANK];
__device__ float g_kv[(size_t)BT * 2 * HD];
__device__ bf16  g_y_hi[(size_t)BT * HD];
__device__ bf16  g_y_lo[(size_t)BT * HD];

// ---------------------------------------------------------------------------
__device__ __forceinline__ void split_bf16(float v, bf16& hi, bf16& lo) {
    hi = __float2bfloat16(v);
    lo = __float2bfloat16(v - __bfloat162float(hi));
}

__device__ __forceinline__ void mma_bf16(float c[4],
    uint32_t a0, uint32_t a1, uint32_t a2, uint32_t a3,
    uint32_t b0, uint32_t b1)
{
    asm volatile(
        "mma.sync.aligned.m16n8k16.row.col.f32.bf16.bf16.f32 "
        "{%0,%1,%2,%3}, {%4,%5,%6,%7}, {%8,%9}, {%0,%1,%2,%3};\n"
        : "+f"(c[0]), "+f"(c[1]), "+f"(c[2]), "+f"(c[3])
        : "r"(a0), "r"(a1), "r"(a2), "r"(a3), "r"(b0), "r"(b1));
}

// ---------------------------------------------------------------------------
// Elementwise split of x (row-major, no transpose): f32 -> hi/lo bf16.
// ---------------------------------------------------------------------------
__global__ __launch_bounds__(256) void convert_kernel(
    const float* __restrict__ in, bf16* __restrict__ oh, bf16* __restrict__ ol,
    int n4)
{
    int i = blockIdx.x * 256 + threadIdx.x;
    if (i >= n4) return;
    float4 v = ((const float4*)in)[i];
    bf16 h0, l0, h1, l1, h2, l2, h3, l3;
    split_bf16(v.x, h0, l0); split_bf16(v.y, h1, l1);
    split_bf16(v.z, h2, l2); split_bf16(v.w, h3, l3);
    __nv_bfloat162 ph0; ph0.x = h0; ph0.y = h1;
    __nv_bfloat162 ph1; ph1.x = h2; ph1.y = h3;
    __nv_bfloat162 pl0; pl0.x = l0; pl0.y = l1;
    __nv_bfloat162 pl1; pl1.x = l2; pl1.y = l3;
    ((__nv_bfloat162*)oh)[i * 2]     = ph0;
    ((__nv_bfloat162*)oh)[i * 2 + 1] = ph1;
    ((__nv_bfloat162*)ol)[i * 2]     = pl0;
    ((__nv_bfloat162*)ol)[i * 2 + 1] = pl1;
}

// ---------------------------------------------------------------------------
// Transpose + split: in [R][C] f32 row-major -> out [C][R] hi/lo bf16.
// ---------------------------------------------------------------------------
__global__ __launch_bounds__(1024) void transpose_convert_kernel(
    const float* __restrict__ in, bf16* __restrict__ oh, bf16* __restrict__ ol,
    int R, int Cc)
{
    __shared__ float tile[32][33];
    int c0 = blockIdx.x * 32;
    int r0 = blockIdx.y * 32;
    int tx = threadIdx.x, ty = threadIdx.y;
    tile[ty][tx] = in[(size_t)(r0 + ty) * Cc + c0 + tx];
    __syncthreads();
    float v = tile[tx][ty];          // = in[r0+tx][c0+ty]
    bf16 h, l; split_bf16(v, h, l);
    size_t o = (size_t)(c0 + ty) * R + r0 + tx;
    oh[o] = h; ol[o] = l;
}

// ---------------------------------------------------------------------------
// GEMM C[M,N] = A[M,K] @ B[N,K]^T with compensated-bf16 operands.
// A: hi/lo [M][K] bf16 row-major; B: hi/lo [N][K] bf16 row-major (i.e. B^T).
// Block 128x128, BK=16, 256 thr, 8 warps (4m x 2n), 32x64 warp tiles.
// Epilogue: optional fp32 C, optional hi/lo bf16 C.
// ---------------------------------------------------------------------------
#define KPAD 24

__global__ __launch_bounds__(256) void gemm_bf16x3_kernel(
    const bf16* __restrict__ Ah, const bf16* __restrict__ Al,
    const bf16* __restrict__ Bh, const bf16* __restrict__ Bl,
    float* __restrict__ Cf, bf16* __restrict__ Chi, bf16* __restrict__ Clo,
    int M, int N, int K)
{
    __shared__ bf16 As[2][2][128 * KPAD];   // [stage][hi/lo][m*KPAD+k]
    __shared__ bf16 Bs[2][2][128 * KPAD];   // [stage][hi/lo][n*KPAD+k]

    const int tid  = threadIdx.x;
    const int row0 = blockIdx.y * 128;
    const int col0 = blockIdx.x * 128;
    const int warp = tid >> 5;
    const int lane = tid & 31;
    const int wm   = warp & 3;          // m-offset = wm*32
    const int wn   = warp >> 2;         // n-offset = wn*64
    const int g    = lane >> 2;
    const int tg   = lane & 3;

    // global->smem mapping: 2 threads per row, 8 bf16 (16B) each
    const int lr = tid >> 1;            // 0..127
    const int lk = (tid & 1) << 3;      // 0 or 8

    const bf16* Ah_p = Ah + (size_t)(row0 + lr) * K + lk;
    const bf16* Al_p = Al + (size_t)(row0 + lr) * K + lk;
    const bf16* Bh_p = Bh + (size_t)(col0 + lr) * K + lk;
    const bf16* Bl_p = Bl + (size_t)(col0 + lr) * K + lk;
    const int sts_off = lr * KPAD + lk;

    float acc[2][8][4];
#pragma unroll
    for (int mt = 0; mt < 2; ++mt)
#pragma unroll
        for (int nt = 0; nt < 8; ++nt)
#pragma unroll
            for (int r = 0; r < 4; ++r) acc[mt][nt][r] = 0.f;

    uint4 rAh, rAl, rBh, rBl;

    // prologue: tile 0
    rAh = *(const uint4*)(Ah_p);
    rAl = *(const uint4*)(Al_p);
    rBh = *(const uint4*)(Bh_p);
    rBl = *(const uint4*)(Bl_p);
    *(uint4*)(&As[0][0][sts_off]) = rAh;
    *(uint4*)(&As[0][1][sts_off]) = rAl;
    *(uint4*)(&Bs[0][0][sts_off]) = rBh;
    *(uint4*)(&Bs[0][1][sts_off]) = rBl;
    __syncthreads();

    const int nk = K >> 4;
    for (int t = 0; t < nk; ++t) {
        const int cur = t & 1;
        const int nxt = cur ^ 1;

        if (t + 1 < nk) {
            const int kt = (t + 1) << 4;
            rAh = *(const uint4*)(Ah_p + kt);
            rAl = *(const uint4*)(Al_p + kt);
            rBh = *(const uint4*)(Bh_p + kt);
            rBl = *(const uint4*)(Bl_p + kt);
        }

        // ---- load fragments from smem ----
        uint32_t afh[2][4], afl[2][4];
#pragma unroll
        for (int mt = 0; mt < 2; ++mt) {
            const int r = wm * 32 + mt * 16 + g;
            const bf16* ph = &As[cur][0][0];
            const bf16* pl = &As[cur][1][0];
            afh[mt][0] = *(const uint32_t*)(ph + r * KPAD + 2 * tg);
            afh[mt][1] = *(const uint32_t*)(ph + (r + 8) * KPAD + 2 * tg);
            afh[mt][2] = *(const uint32_t*)(ph + r * KPAD + 2 * tg + 8);
            afh[mt][3] = *(const uint32_t*)(ph + (r + 8) * KPAD + 2 * tg + 8);
            afl[mt][0] = *(const uint32_t*)(pl + r * KPAD + 2 * tg);
            afl[mt][1] = *(const uint32_t*)(pl + (r + 8) * KPAD + 2 * tg);
            afl[mt][2] = *(const uint32_t*)(pl + r * KPAD + 2 * tg + 8);
            afl[mt][3] = *(const uint32_t*)(pl + (r + 8) * KPAD + 2 * tg + 8);
        }
        uint32_t bfh[8][2], bfl[8][2];
#pragma unroll
        for (int nt = 0; nt < 8; ++nt) {
            const int n = wn * 64 + nt * 8 + g;
            const bf16* ph = &Bs[cur][0][0];
            const bf16* pl = &Bs[cur][1][0];
            bfh[nt][0] = *(const uint32_t*)(ph + n * KPAD + 2 * tg);
            bfh[nt][1] = *(const uint32_t*)(ph + n * KPAD + 2 * tg + 8);
            bfl[nt][0] = *(const uint32_t*)(pl + n * KPAD + 2 * tg);
            bfl[nt][1] = *(const uint32_t*)(pl + n * KPAD + 2 * tg + 8);
        }

        // ---- 3-term compensated MMA ----
#pragma unroll
        for (int mt = 0; mt < 2; ++mt)
#pragma unroll
            for (int nt = 0; nt < 8; ++nt) {
                mma_bf16(acc[mt][nt], afh[mt][0], afh[mt][1], afh[mt][2], afh[mt][3],
                         bfl[nt][0], bfl[nt][1]);
                mma_bf16(acc[mt][nt], afl[mt][0], afl[mt][1], afl[mt][2], afl[mt][3],
                         bfh[nt][0], bfh[nt][1]);
                mma_bf16(acc[mt][nt], afh[mt][0], afh[mt][1], afh[mt][2], afh[mt][3],
                         bfh[nt][0], bfh[nt][1]);
            }

        if (t + 1 < nk) {
            *(uint4*)(&As[nxt][0][sts_off]) = rAh;
            *(uint4*)(&As[nxt][1][sts_off]) = rAl;
            *(uint4*)(&Bs[nxt][0][sts_off]) = rBh;
            *(uint4*)(&Bs[nxt][1][sts_off]) = rBl;
        }
        __syncthreads();
    }

    // ---- epilogue ----
#pragma unroll
    for (int mt = 0; mt < 2; ++mt) {
#pragma unroll
        for (int nt = 0; nt < 8; ++nt) {
            const int r  = row0 + wm * 32 + mt * 16 + g;
            const int cc = col0 + wn * 64 + nt * 8 + 2 * tg;
            float* a = acc[mt][nt];
            if (Cf) {
                *(float2*)(Cf + (size_t)r * N + cc)       = make_float2(a[0], a[1]);
                *(float2*)(Cf + (size_t)(r + 8) * N + cc) = make_float2(a[2], a[3]);
            }
            if (Chi) {
                bf16 h0, l0, h1, l1;
                split_bf16(a[0], h0, l0); split_bf16(a[1], h1, l1);
                __nv_bfloat162 ph; ph.x = h0; ph.y = h1;
                __nv_bfloat162 pl; pl.x = l0; pl.y = l1;
                *(__nv_bfloat162*)(Chi + (size_t)r * N + cc) = ph;
                *(__nv_bfloat162*)(Clo + (size_t)r * N + cc) = pl;
                split_bf16(a[2], h0, l0); split_bf16(a[3], h1, l1);
                ph.x = h0; ph.y = h1; pl.x = l0; pl.y = l1;
                *(__nv_bfloat162*)(Chi + (size_t)(r + 8) * N + cc) = ph;
                *(__nv_bfloat162*)(Clo + (size_t)(r + 8) * N + cc) = pl;
            }
        }
    }
}

// ---------------------------------------------------------------------------
// Causal attention: one block per (b,h), one thread per query row (T=256).
// Online softmax; K/V chunks of 64 rows staged in SMEM.
// Writes y as hi/lo bf16 (feeds the final GEMM).
// ---------------------------------------------------------------------------
__global__ __launch_bounds__(256) void attn_kernel(
    const float* __restrict__ qb, const float* __restrict__ kvb,
    bf16* __restrict__ yh, bf16* __restrict__ yl)
{
    __shared__ float Ks[64][64];
    __shared__ float Vs[64][64];

    const int b = blockIdx.x >> 4;
    const int h = blockIdx.x & 15;
    const int i = threadIdx.x;

    const float* qrow = qb + ((size_t)(b * TT + i)) * HD + h * HS;
    float q[64];
#pragma unroll
    for (int d = 0; d < 64; ++d) q[d] = qrow[d];

    float m = -1e30f, l = 0.f;
    float acc[64];
#pragma unroll
    for (int d = 0; d < 64; ++d) acc[d] = 0.f;

    for (int c = 0; c < 4; ++c) {
        __syncthreads();
#pragma unroll
        for (int e = 0; e < 4; ++e) {
            int idx = threadIdx.x + e * 256;
            int r   = idx >> 4;
            int c4  = (idx & 15) << 2;
            const float* kvrow =
                kvb + ((size_t)(b * TT + c * 64 + r)) * (2 * HD) + h * HS;
            *(float4*)(&Ks[r][c4]) = *(const float4*)(kvrow + c4);
            *(float4*)(&Vs[r][c4]) = *(const float4*)(kvrow + HD + c4);
        }
        __syncthreads();

        int jmax = i - c * 64 + 1;
        if (jmax > 64) jmax = 64;
        for (int jj = 0; jj < jmax; ++jj) {
            float s = 0.f;
#pragma unroll
            for (int d4 = 0; d4 < 16; ++d4) {
                float4 k4 = *(const float4*)(&Ks[jj][d4 << 2]);
                s += q[d4 * 4 + 0] * k4.x + q[d4 * 4 + 1] * k4.y +
                     q[d4 * 4 + 2] * k4.z + q[d4 * 4 + 3] * k4.w;
            }
            s *= 0.125f;
            if (s > m) {
                float f = __expf(m - s);
                l *= f;
#pragma unroll
                for (int d = 0; d < 64; ++d) acc[d] *= f;
                m = s;
            }
            float p = __expf(s - m);
            l += p;
#pragma unroll
            for (int d4 = 0; d4 < 16; ++d4) {
                float4 v4 = *(const float4*)(&Vs[jj][d4 << 2]);
                acc[d4 * 4 + 0] += p * v4.x;
                acc[d4 * 4 + 1] += p * v4.y;
                acc[d4 * 4 + 2] += p * v4.z;
                acc[d4 * 4 + 3] += p * v4.w;
            }
        }
    }

    float inv = 1.0f / l;
    size_t yo = ((size_t)(b * TT + i)) * HD + h * HS;
#pragma unroll
    for (int d = 0; d < 64; d += 2) {
        bf16 h0, l0, h1, l1;
        split_bf16(acc[d] * inv, h0, l0);
        split_bf16(acc[d + 1] * inv, h1, l1);
        __nv_bfloat162 ph; ph.x = h0; ph.y = h1;
        __nv_bfloat162 pl; pl.x = l0; pl.y = l1;
        *(__nv_bfloat162*)(yh + yo + d) = ph;
        *(__nv_bfloat162*)(yl + yo + d) = pl;
    }
}

// ---------------------------------------------------------------------------
// kernel_launch — inputs: x, w_kv_down, w_kv_up, w_q, w_out (all fp32)
// ---------------------------------------------------------------------------
extern "C" void kernel_launch(void* const* d_in, const int* in_sizes, int n_in,
                              void* d_out, int out_size)
{
    const float* x         = (const float*)d_in[0];
    const float* w_kv_down = (const float*)d_in[1];
    const float* w_kv_up   = (const float*)d_in[2];
    const float* w_q       = (const float*)d_in[3];
    const float* w_out     = (const float*)d_in[4];
    float* out             = (float*)d_out;

    bf16 *x_hi, *x_lo, *wq_hi, *wq_lo, *wkvd_hi, *wkvd_lo;
    bf16 *wkvu_hi, *wkvu_lo, *wo_hi, *wo_lo;
    bf16 *lat_hi, *lat_lo, *y_hi, *y_lo;
    float *q, *kv;
    cudaGetSymbolAddress((void**)&x_hi,   g_x_hi);
    cudaGetSymbolAddress((void**)&x_lo,   g_x_lo);
    cudaGetSymbolAddress((void**)&wq_hi,  g_wq_hi);
    cudaGetSymbolAddress((void**)&wq_lo,  g_wq_lo);
    cudaGetSymbolAddress((void**)&wkvd_hi,g_wkvd_hi);
    cudaGetSymbolAddress((void**)&wkvd_lo,g_wkvd_lo);
    cudaGetSymbolAddress((void**)&wkvu_hi,g_wkvu_hi);
    cudaGetSymbolAddress((void**)&wkvu_lo,g_wkvu_lo);
    cudaGetSymbolAddress((void**)&wo_hi,  g_wo_hi);
    cudaGetSymbolAddress((void**)&wo_lo,  g_wo_lo);
    cudaGetSymbolAddress((void**)&q,      g_q);
    cudaGetSymbolAddress((void**)&lat_hi, g_lat_hi);
    cudaGetSymbolAddress((void**)&lat_lo, g_lat_lo);
    cudaGetSymbolAddress((void**)&kv,     g_kv);
    cudaGetSymbolAddress((void**)&y_hi,   g_y_hi);
    cudaGetSymbolAddress((void**)&y_lo,   g_y_lo);

    // ---- prepass: splits + weight transposes ----
    convert_kernel<<<(BT * C_DIM / 4 + 255) / 256, 256>>>(x, x_hi, x_lo, BT * C_DIM / 4);
    dim3 tb(32, 32);
    transpose_convert_kernel<<<dim3(HD / 32, C_DIM / 32), tb>>>(w_q, wq_hi, wq_lo, C_DIM, HD);
    transpose_convert_kernel<<<dim3(RANK / 32, C_DIM / 32), tb>>>(w_kv_down, wkvd_hi, wkvd_lo, C_DIM, RANK);
    transpose_convert_kernel<<<dim3(2 * HD / 32, RANK / 32), tb>>>(w_kv_up, wkvu_hi, wkvu_lo, RANK, 2 * HD);
    transpose_convert_kernel<<<dim3(C_DIM / 32, HD / 32), tb>>>(w_out, wo_hi, wo_lo, HD, C_DIM);

    dim3 blk(256);
    // q = x @ w_q (fp32 out)
    gemm_bf16x3_kernel<<<dim3(HD / 128, BT / 128), blk>>>(
        x_hi, x_lo, wq_hi, wq_lo, q, nullptr, nullptr, BT, HD, C_DIM);
    // latent = x @ w_kv_down (hi/lo out only)
    gemm_bf16x3_kernel<<<dim3(RANK / 128, BT / 128), blk>>>(
        x_hi, x_lo, wkvd_hi, wkvd_lo, nullptr, lat_hi, lat_lo, BT, RANK, C_DIM);
    // kv = latent @ w_kv_up (fp32 out)
    gemm_bf16x3_kernel<<<dim3(2 * HD / 128, BT / 128), blk>>>(
        lat_hi, lat_lo, wkvu_hi, wkvu_lo, kv, nullptr, nullptr, BT, 2 * HD, RANK);
    // attention (writes y hi/lo)
    attn_kernel<<<64 * NH, blk>>>(q, kv, y_hi, y_lo);
    // out = y @ w_out (fp32 out -> d_out)
    gemm_bf16x3_kernel<<<dim3(C_DIM / 128, BT / 128), blk>>>(
        y_hi, y_lo, wo_hi, wo_lo, out, nullptr, nullptr, BT, C_DIM, HD);
}

// round 6
// speedup vs baseline: 1.2096x; 1.2096x over previous
#include <cuda_runtime.h>
#include <cuda_bf16.h>
#include <stdint.h>

#define BT     16384   // B*T
#define C_DIM  1024
#define HD     1024    // N_HEAD * HEAD_SIZE
#define RANK   128
#define TT     256     // T
#define NH     16
#define HS     64

typedef __nv_bfloat16 bf16;

// ---------------- scratch (device globals; no allocation allowed) ----------
__device__ bf16  g_x_hi[(size_t)BT * C_DIM];
__device__ bf16  g_x_lo[(size_t)BT * C_DIM];
__device__ bf16  g_wq_hi[(size_t)HD * C_DIM];      // [N][K] transposed
__device__ bf16  g_wq_lo[(size_t)HD * C_DIM];
__device__ bf16  g_wkvd_hi[(size_t)RANK * C_DIM];
__device__ bf16  g_wkvd_lo[(size_t)RANK * C_DIM];
__device__ bf16  g_wkvu_hi[(size_t)2 * HD * RANK];
__device__ bf16  g_wkvu_lo[(size_t)2 * HD * RANK];
__device__ bf16  g_wo_hi[(size_t)C_DIM * HD];
__device__ bf16  g_wo_lo[(size_t)C_DIM * HD];
__device__ float g_q[(size_t)BT * HD];
__device__ bf16  g_lat_hi[(size_t)BT * RANK];
__device__ bf16  g_lat_lo[(size_t)BT * RANK];
__device__ float g_kv[(size_t)BT * 2 * HD];
__device__ bf16  g_y_hi[(size_t)BT * HD];
__device__ bf16  g_y_lo[(size_t)BT * HD];

// ---------------------------------------------------------------------------
__device__ __forceinline__ void split_bf16(float v, bf16& hi, bf16& lo) {
    hi = __float2bfloat16(v);
    lo = __float2bfloat16(v - __bfloat162float(hi));
}

__device__ __forceinline__ uint32_t smem_u32(const void* p) {
    uint32_t a;
    asm("{ .reg .u64 t; cvta.to.shared.u64 t, %1; cvt.u32.u64 %0, t; }"
        : "=r"(a) : "l"(p));
    return a;
}

__device__ __forceinline__ void mma_bf16(float c[4],
    uint32_t a0, uint32_t a1, uint32_t a2, uint32_t a3,
    uint32_t b0, uint32_t b1)
{
    asm volatile(
        "mma.sync.aligned.m16n8k16.row.col.f32.bf16.bf16.f32 "
        "{%0,%1,%2,%3}, {%4,%5,%6,%7}, {%8,%9}, {%0,%1,%2,%3};\n"
        : "+f"(c[0]), "+f"(c[1]), "+f"(c[2]), "+f"(c[3])
        : "r"(a0), "r"(a1), "r"(a2), "r"(a3), "r"(b0), "r"(b1));
}

__device__ __forceinline__ void ldsm_x4(uint32_t& r0, uint32_t& r1,
                                        uint32_t& r2, uint32_t& r3, uint32_t a)
{
    asm volatile("ldmatrix.sync.aligned.m8n8.x4.shared.b16 {%0,%1,%2,%3}, [%4];"
                 : "=r"(r0), "=r"(r1), "=r"(r2), "=r"(r3) : "r"(a));
}

__device__ __forceinline__ void cp16(uint32_t dst, const void* src) {
    asm volatile("cp.async.cg.shared.global [%0], [%1], 16;"
                 :: "r"(dst), "l"(src) : "memory");
}
__device__ __forceinline__ void cp_commit() {
    asm volatile("cp.async.commit_group;" ::: "memory");
}
template <int N>
__device__ __forceinline__ void cp_wait() {
    asm volatile("cp.async.wait_group %0;" :: "n"(N) : "memory");
}

// ---------------------------------------------------------------------------
// prepass kernels
// ---------------------------------------------------------------------------
__global__ __launch_bounds__(256) void convert_kernel(
    const float* __restrict__ in, bf16* __restrict__ oh, bf16* __restrict__ ol,
    int n4)
{
    int i = blockIdx.x * 256 + threadIdx.x;
    if (i >= n4) return;
    float4 v = ((const float4*)in)[i];
    bf16 h0, l0, h1, l1, h2, l2, h3, l3;
    split_bf16(v.x, h0, l0); split_bf16(v.y, h1, l1);
    split_bf16(v.z, h2, l2); split_bf16(v.w, h3, l3);
    __nv_bfloat162 ph0; ph0.x = h0; ph0.y = h1;
    __nv_bfloat162 ph1; ph1.x = h2; ph1.y = h3;
    __nv_bfloat162 pl0; pl0.x = l0; pl0.y = l1;
    __nv_bfloat162 pl1; pl1.x = l2; pl1.y = l3;
    ((__nv_bfloat162*)oh)[i * 2]     = ph0;
    ((__nv_bfloat162*)oh)[i * 2 + 1] = ph1;
    ((__nv_bfloat162*)ol)[i * 2]     = pl0;
    ((__nv_bfloat162*)ol)[i * 2 + 1] = pl1;
}

__global__ __launch_bounds__(1024) void transpose_convert_kernel(
    const float* __restrict__ in, bf16* __restrict__ oh, bf16* __restrict__ ol,
    int R, int Cc)
{
    __shared__ float tile[32][33];
    int c0 = blockIdx.x * 32;
    int r0 = blockIdx.y * 32;
    int tx = threadIdx.x, ty = threadIdx.y;
    tile[ty][tx] = in[(size_t)(r0 + ty) * Cc + c0 + tx];
    __syncthreads();
    float v = tile[tx][ty];
    bf16 h, l; split_bf16(v, h, l);
    size_t o = (size_t)(c0 + ty) * R + r0 + tx;
    oh[o] = h; ol[o] = l;
}

// ---------------------------------------------------------------------------
// GEMM C[M,N] = A[M,K] @ B[N,K]^T, compensated bf16 (3-term), mma.sync.
// CTA 128x128, BK=16, 256 thr, 8 warps (4m x 2n), 32x64 warp tiles.
// cp.async 4-stage pipeline, ldmatrix fragment loads.
// smem stage (24576B): Ah(6144) Al(6144) Bh(6144) Bl(6144); rows 48B
//   (16 bf16 data + 8 bf16 pad).
// ---------------------------------------------------------------------------
#define KPADB     48      // row stride bytes
#define REG_SZ    6144    // per-region bytes (128 rows * 48)
#define STG_SZ    24576   // stage bytes
#define NSTAGE    4
#define GEMM_SMEM (NSTAGE * STG_SZ)

struct FillPtrs { const bf16* p[4]; };

__device__ __forceinline__ void fill_stage(
    uint32_t sb, int stage, int kt, const FillPtrs& fp, int K, int tid)
{
    const int row  = tid >> 1;
    const int half = tid & 1;
    const uint32_t dbase = sb + stage * STG_SZ + row * KPADB + half * 16;
#pragma unroll
    for (int reg = 0; reg < 4; ++reg) {
        const bf16* gp = fp.p[reg] + (size_t)row * K + kt + half * 8;
        cp16(dbase + reg * REG_SZ, gp);
    }
    cp_commit();
}

__global__ __launch_bounds__(256) void gemm_bf16x3_kernel(
    const bf16* __restrict__ Ah, const bf16* __restrict__ Al,
    const bf16* __restrict__ Bh, const bf16* __restrict__ Bl,
    float* __restrict__ Cf, bf16* __restrict__ Chi, bf16* __restrict__ Clo,
    int M, int N, int K)
{
    extern __shared__ char smem[];
    const uint32_t sb = smem_u32(smem);

    const int tid  = threadIdx.x;
    const int warp = tid >> 5;
    const int lid  = tid & 31;
    const int row0 = blockIdx.y * 128;
    const int col0 = blockIdx.x * 128;
    const int wm   = warp & 3;          // m-offset = wm*32
    const int wn   = warp >> 2;         // n-offset = wn*64
    const int g    = lid >> 2;
    const int tg   = lid & 3;
    const int m8   = lid >> 3;          // ldmatrix matrix index 0..3
    const int rl   = lid & 7;

    FillPtrs fp;
    fp.p[0] = Ah + (size_t)row0 * K;
    fp.p[1] = Al + (size_t)row0 * K;
    fp.p[2] = Bh + (size_t)col0 * K;
    fp.p[3] = Bl + (size_t)col0 * K;

    // ldmatrix per-lane base addresses (within stage 0)
    // A (mt, hl): matrices [rows0-7,k0-7][rows8-15,k0-7][rows0-7,k8-15][rows8-15,k8-15]
    uint32_t a_addr[2][2];
#pragma unroll
    for (int mt = 0; mt < 2; ++mt)
#pragma unroll
        for (int hl = 0; hl < 2; ++hl) {
            int r = wm * 32 + mt * 16 + (m8 & 1) * 8 + rl;
            a_addr[mt][hl] = sb + hl * REG_SZ + r * KPADB + ((m8 >> 1) * 8) * 2;
        }
    // B (np covering nt=2np..2np+1, hl): matrices [n0-7,k0-7][n0-7,k8-15][n8-15,k0-7][n8-15,k8-15]
    uint32_t b_addr[4][2];
#pragma unroll
    for (int np = 0; np < 4; ++np)
#pragma unroll
        for (int hl = 0; hl < 2; ++hl) {
            int r = wn * 64 + np * 16 + (m8 >> 1) * 8 + rl;
            b_addr[np][hl] = sb + (2 + hl) * REG_SZ + r * KPADB + ((m8 & 1) * 8) * 2;
        }

    float acc[2][8][4];
#pragma unroll
    for (int mt = 0; mt < 2; ++mt)
#pragma unroll
        for (int nt = 0; nt < 8; ++nt)
#pragma unroll
            for (int r = 0; r < 4; ++r) acc[mt][nt][r] = 0.f;

    const int nk = K >> 4;

    // prologue: fill up to 3 stages
#pragma unroll
    for (int s = 0; s < NSTAGE - 1; ++s)
        if (s < nk) fill_stage(sb, s, s << 4, fp, K, tid);

    for (int t = 0; t < nk; ++t) {
        // wait until stage (t&3) is complete, accounting for pipeline tail
        if (t + 3 <= nk)      cp_wait<2>();
        else if (t + 2 == nk) cp_wait<1>();
        else                  cp_wait<0>();
        __syncthreads();

        const uint32_t soff = (uint32_t)(t & 3) * STG_SZ;

        uint32_t ah[2][4], al[2][4];
#pragma unroll
        for (int mt = 0; mt < 2; ++mt) {
            ldsm_x4(ah[mt][0], ah[mt][1], ah[mt][2], ah[mt][3], a_addr[mt][0] + soff);
            ldsm_x4(al[mt][0], al[mt][1], al[mt][2], al[mt][3], a_addr[mt][1] + soff);
        }

#pragma unroll
        for (int np = 0; np < 4; ++np) {
            uint32_t bh[4], bl[4];
            ldsm_x4(bh[0], bh[1], bh[2], bh[3], b_addr[np][0] + soff);
            ldsm_x4(bl[0], bl[1], bl[2], bl[3], b_addr[np][1] + soff);
#pragma unroll
            for (int sub = 0; sub < 2; ++sub) {
                const int nt = np * 2 + sub;
#pragma unroll
                for (int mt = 0; mt < 2; ++mt) {
                    mma_bf16(acc[mt][nt], ah[mt][0], ah[mt][1], ah[mt][2], ah[mt][3],
                             bl[sub * 2], bl[sub * 2 + 1]);
                    mma_bf16(acc[mt][nt], al[mt][0], al[mt][1], al[mt][2], al[mt][3],
                             bh[sub * 2], bh[sub * 2 + 1]);
                    mma_bf16(acc[mt][nt], ah[mt][0], ah[mt][1], ah[mt][2], ah[mt][3],
                             bh[sub * 2], bh[sub * 2 + 1]);
                }
            }
        }

        if (t + NSTAGE - 1 < nk)
            fill_stage(sb, (t + 3) & 3, (t + 3) << 4, fp, K, tid);
    }

    // ---- epilogue ----
#pragma unroll
    for (int mt = 0; mt < 2; ++mt) {
#pragma unroll
        for (int nt = 0; nt < 8; ++nt) {
            const int r  = row0 + wm * 32 + mt * 16 + g;
            const int cc = col0 + wn * 64 + nt * 8 + 2 * tg;
            float* a = acc[mt][nt];
            if (Cf) {
                *(float2*)(Cf + (size_t)r * N + cc)       = make_float2(a[0], a[1]);
                *(float2*)(Cf + (size_t)(r + 8) * N + cc) = make_float2(a[2], a[3]);
            }
            if (Chi) {
                bf16 h0, l0, h1, l1;
                split_bf16(a[0], h0, l0); split_bf16(a[1], h1, l1);
                __nv_bfloat162 ph; ph.x = h0; ph.y = h1;
                __nv_bfloat162 pl; pl.x = l0; pl.y = l1;
                *(__nv_bfloat162*)(Chi + (size_t)r * N + cc) = ph;
                *(__nv_bfloat162*)(Clo + (size_t)r * N + cc) = pl;
                split_bf16(a[2], h0, l0); split_bf16(a[3], h1, l1);
                ph.x = h0; ph.y = h1; pl.x = l0; pl.y = l1;
                *(__nv_bfloat162*)(Chi + (size_t)(r + 8) * N + cc) = ph;
                *(__nv_bfloat162*)(Clo + (size_t)(r + 8) * N + cc) = pl;
            }
        }
    }
}

// ---------------------------------------------------------------------------
// Causal attention: one block per (b,h), one thread per query row (T=256).
// ---------------------------------------------------------------------------
__global__ __launch_bounds__(256) void attn_kernel(
    const float* __restrict__ qb, const float* __restrict__ kvb,
    bf16* __restrict__ yh, bf16* __restrict__ yl)
{
    __shared__ float Ks[64][64];
    __shared__ float Vs[64][64];

    const int b = blockIdx.x >> 4;
    const int h = blockIdx.x & 15;
    const int i = threadIdx.x;

    const float* qrow = qb + ((size_t)(b * TT + i)) * HD + h * HS;
    float q[64];
#pragma unroll
    for (int d = 0; d < 64; ++d) q[d] = qrow[d];

    float m = -1e30f, l = 0.f;
    float acc[64];
#pragma unroll
    for (int d = 0; d < 64; ++d) acc[d] = 0.f;

    for (int c = 0; c < 4; ++c) {
        __syncthreads();
#pragma unroll
        for (int e = 0; e < 4; ++e) {
            int idx = threadIdx.x + e * 256;
            int r   = idx >> 4;
            int c4  = (idx & 15) << 2;
            const float* kvrow =
                kvb + ((size_t)(b * TT + c * 64 + r)) * (2 * HD) + h * HS;
            *(float4*)(&Ks[r][c4]) = *(const float4*)(kvrow + c4);
            *(float4*)(&Vs[r][c4]) = *(const float4*)(kvrow + HD + c4);
        }
        __syncthreads();

        int jmax = i - c * 64 + 1;
        if (jmax > 64) jmax = 64;
        for (int jj = 0; jj < jmax; ++jj) {
            float s = 0.f;
#pragma unroll
            for (int d4 = 0; d4 < 16; ++d4) {
                float4 k4 = *(const float4*)(&Ks[jj][d4 << 2]);
                s += q[d4 * 4 + 0] * k4.x + q[d4 * 4 + 1] * k4.y +
                     q[d4 * 4 + 2] * k4.z + q[d4 * 4 + 3] * k4.w;
            }
            s *= 0.125f;
            if (s > m) {
                float f = __expf(m - s);
                l *= f;
#pragma unroll
                for (int d = 0; d < 64; ++d) acc[d] *= f;
                m = s;
            }
            float p = __expf(s - m);
            l += p;
#pragma unroll
            for (int d4 = 0; d4 < 16; ++d4) {
                float4 v4 = *(const float4*)(&Vs[jj][d4 << 2]);
                acc[d4 * 4 + 0] += p * v4.x;
                acc[d4 * 4 + 1] += p * v4.y;
                acc[d4 * 4 + 2] += p * v4.z;
                acc[d4 * 4 + 3] += p * v4.w;
            }
        }
    }

    float inv = 1.0f / l;
    size_t yo = ((size_t)(b * TT + i)) * HD + h * HS;
#pragma unroll
    for (int d = 0; d < 64; d += 2) {
        bf16 h0, l0, h1, l1;
        split_bf16(acc[d] * inv, h0, l0);
        split_bf16(acc[d + 1] * inv, h1, l1);
        __nv_bfloat162 ph; ph.x = h0; ph.y = h1;
        __nv_bfloat162 pl; pl.x = l0; pl.y = l1;
        *(__nv_bfloat162*)(yh + yo + d) = ph;
        *(__nv_bfloat162*)(yl + yo + d) = pl;
    }
}

// ---------------------------------------------------------------------------
// kernel_launch — inputs: x, w_kv_down, w_kv_up, w_q, w_out (all fp32)
// ---------------------------------------------------------------------------
extern "C" void kernel_launch(void* const* d_in, const int* in_sizes, int n_in,
                              void* d_out, int out_size)
{
    const float* x         = (const float*)d_in[0];
    const float* w_kv_down = (const float*)d_in[1];
    const float* w_kv_up   = (const float*)d_in[2];
    const float* w_q       = (const float*)d_in[3];
    const float* w_out     = (const float*)d_in[4];
    float* out             = (float*)d_out;

    bf16 *x_hi, *x_lo, *wq_hi, *wq_lo, *wkvd_hi, *wkvd_lo;
    bf16 *wkvu_hi, *wkvu_lo, *wo_hi, *wo_lo;
    bf16 *lat_hi, *lat_lo, *y_hi, *y_lo;
    float *q, *kv;
    cudaGetSymbolAddress((void**)&x_hi,   g_x_hi);
    cudaGetSymbolAddress((void**)&x_lo,   g_x_lo);
    cudaGetSymbolAddress((void**)&wq_hi,  g_wq_hi);
    cudaGetSymbolAddress((void**)&wq_lo,  g_wq_lo);
    cudaGetSymbolAddress((void**)&wkvd_hi,g_wkvd_hi);
    cudaGetSymbolAddress((void**)&wkvd_lo,g_wkvd_lo);
    cudaGetSymbolAddress((void**)&wkvu_hi,g_wkvu_hi);
    cudaGetSymbolAddress((void**)&wkvu_lo,g_wkvu_lo);
    cudaGetSymbolAddress((void**)&wo_hi,  g_wo_hi);
    cudaGetSymbolAddress((void**)&wo_lo,  g_wo_lo);
    cudaGetSymbolAddress((void**)&q,      g_q);
    cudaGetSymbolAddress((void**)&lat_hi, g_lat_hi);
    cudaGetSymbolAddress((void**)&lat_lo, g_lat_lo);
    cudaGetSymbolAddress((void**)&kv,     g_kv);
    cudaGetSymbolAddress((void**)&y_hi,   g_y_hi);
    cudaGetSymbolAddress((void**)&y_lo,   g_y_lo);

    cudaFuncSetAttribute(gemm_bf16x3_kernel,
        cudaFuncAttributeMaxDynamicSharedMemorySize, GEMM_SMEM);

    // ---- prepass: splits + weight transposes ----
    convert_kernel<<<(BT * C_DIM / 4 + 255) / 256, 256>>>(x, x_hi, x_lo, BT * C_DIM / 4);
    dim3 tb(32, 32);
    transpose_convert_kernel<<<dim3(HD / 32, C_DIM / 32), tb>>>(w_q, wq_hi, wq_lo, C_DIM, HD);
    transpose_convert_kernel<<<dim3(RANK / 32, C_DIM / 32), tb>>>(w_kv_down, wkvd_hi, wkvd_lo, C_DIM, RANK);
    transpose_convert_kernel<<<dim3(2 * HD / 32, RANK / 32), tb>>>(w_kv_up, wkvu_hi, wkvu_lo, RANK, 2 * HD);
    transpose_convert_kernel<<<dim3(C_DIM / 32, HD / 32), tb>>>(w_out, wo_hi, wo_lo, HD, C_DIM);

    dim3 blk(256);
    // q = x @ w_q (fp32 out)
    gemm_bf16x3_kernel<<<dim3(HD / 128, BT / 128), blk, GEMM_SMEM>>>(
        x_hi, x_lo, wq_hi, wq_lo, q, nullptr, nullptr, BT, HD, C_DIM);
    // latent = x @ w_kv_down (hi/lo out only)
    gemm_bf16x3_kernel<<<dim3(RANK / 128, BT / 128), blk, GEMM_SMEM>>>(
        x_hi, x_lo, wkvd_hi, wkvd_lo, nullptr, lat_hi, lat_lo, BT, RANK, C_DIM);
    // kv = latent @ w_kv_up (fp32 out)
    gemm_bf16x3_kernel<<<dim3(2 * HD / 128, BT / 128), blk, GEMM_SMEM>>>(
        lat_hi, lat_lo, wkvu_hi, wkvu_lo, kv, nullptr, nullptr, BT, 2 * HD, RANK);
    // attention (writes y hi/lo)
    attn_kernel<<<64 * NH, blk>>>(q, kv, y_hi, y_lo);
    // out = y @ w_out (fp32 out -> d_out)
    gemm_bf16x3_kernel<<<dim3(C_DIM / 128, BT / 128), blk, GEMM_SMEM>>>(
        y_hi, y_lo, wo_hi, wo_lo, out, nullptr, nullptr, BT, C_DIM, HD);
}

// round 7
// speedup vs baseline: 1.3305x; 1.1000x over previous
#include <cuda_runtime.h>
#include <cuda_fp16.h>
#include <stdint.h>

#define BT     16384   // B*T
#define C_DIM  1024
#define HD     1024    // N_HEAD * HEAD_SIZE
#define RANK   128
#define TT     256     // T
#define NH     16
#define HS     64

typedef __half fp16;

// ---------------- scratch (device globals; no allocation allowed) ----------
__device__ fp16  g_x_hi[(size_t)BT * C_DIM];
__device__ fp16  g_x_lo[(size_t)BT * C_DIM];
__device__ fp16  g_wq_hi[(size_t)HD * C_DIM];      // [N][K] transposed
__device__ fp16  g_wq_lo[(size_t)HD * C_DIM];
__device__ fp16  g_wkvd_hi[(size_t)RANK * C_DIM];
__device__ fp16  g_wkvd_lo[(size_t)RANK * C_DIM];
__device__ fp16  g_wkvu_hi[(size_t)2 * HD * RANK];
__device__ fp16  g_wkvu_lo[(size_t)2 * HD * RANK];
__device__ fp16  g_wo_hi[(size_t)C_DIM * HD];
__device__ fp16  g_wo_lo[(size_t)C_DIM * HD];
__device__ float g_q[(size_t)BT * HD];
__device__ fp16  g_lat_hi[(size_t)BT * RANK];
__device__ fp16  g_lat_lo[(size_t)BT * RANK];
__device__ float g_kv[(size_t)BT * 2 * HD];
__device__ fp16  g_y_h[(size_t)BT * HD];

// ---------------------------------------------------------------------------
__device__ __forceinline__ void split_fp16(float v, fp16& hi, fp16& lo) {
    hi = __float2half_rn(v);
    lo = __float2half_rn(v - __half2float(hi));
}

__device__ __forceinline__ uint32_t smem_u32(const void* p) {
    uint32_t a;
    asm("{ .reg .u64 t; cvta.to.shared.u64 t, %1; cvt.u32.u64 %0, t; }"
        : "=r"(a) : "l"(p));
    return a;
}

__device__ __forceinline__ void mma_fp16(float c[4],
    uint32_t a0, uint32_t a1, uint32_t a2, uint32_t a3,
    uint32_t b0, uint32_t b1)
{
    asm volatile(
        "mma.sync.aligned.m16n8k16.row.col.f32.f16.f16.f32 "
        "{%0,%1,%2,%3}, {%4,%5,%6,%7}, {%8,%9}, {%0,%1,%2,%3};\n"
        : "+f"(c[0]), "+f"(c[1]), "+f"(c[2]), "+f"(c[3])
        : "r"(a0), "r"(a1), "r"(a2), "r"(a3), "r"(b0), "r"(b1));
}

__device__ __forceinline__ void ldsm_x4(uint32_t& r0, uint32_t& r1,
                                        uint32_t& r2, uint32_t& r3, uint32_t a)
{
    asm volatile("ldmatrix.sync.aligned.m8n8.x4.shared.b16 {%0,%1,%2,%3}, [%4];"
                 : "=r"(r0), "=r"(r1), "=r"(r2), "=r"(r3) : "r"(a));
}

__device__ __forceinline__ void cp16(uint32_t dst, const void* src) {
    asm volatile("cp.async.cg.shared.global [%0], [%1], 16;"
                 :: "r"(dst), "l"(src) : "memory");
}
__device__ __forceinline__ void cp_commit() {
    asm volatile("cp.async.commit_group;" ::: "memory");
}
template <int N>
__device__ __forceinline__ void cp_wait() {
    asm volatile("cp.async.wait_group %0;" :: "n"(N) : "memory");
}

// ---------------------------------------------------------------------------
// prepass: x split (hi/lo fp16)
// ---------------------------------------------------------------------------
__global__ __launch_bounds__(256) void convert_kernel(
    const float* __restrict__ in, fp16* __restrict__ oh, fp16* __restrict__ ol,
    int n4)
{
    int i = blockIdx.x * 256 + threadIdx.x;
    if (i >= n4) return;
    float4 v = ((const float4*)in)[i];
    fp16 h0, l0, h1, l1, h2, l2, h3, l3;
    split_fp16(v.x, h0, l0); split_fp16(v.y, h1, l1);
    split_fp16(v.z, h2, l2); split_fp16(v.w, h3, l3);
    __half2 ph0 = __halves2half2(h0, h1);
    __half2 ph1 = __halves2half2(h2, h3);
    __half2 pl0 = __halves2half2(l0, l1);
    __half2 pl1 = __halves2half2(l2, l3);
    ((__half2*)oh)[i * 2]     = ph0;
    ((__half2*)oh)[i * 2 + 1] = ph1;
    ((__half2*)ol)[i * 2]     = pl0;
    ((__half2*)ol)[i * 2 + 1] = pl1;
}

// ---------------------------------------------------------------------------
// prepass: ALL four weight transposes fused into one launch.
// in [R][C] f32 row-major -> out [C][R] hi/lo fp16.
// 1D grid; segment decode by blockIdx.x.
// ---------------------------------------------------------------------------
__global__ __launch_bounds__(1024) void weights_kernel(
    const float* __restrict__ wq,  fp16* __restrict__ wq_h,  fp16* __restrict__ wq_l,
    const float* __restrict__ wkd, fp16* __restrict__ wkd_h, fp16* __restrict__ wkd_l,
    const float* __restrict__ wku, fp16* __restrict__ wku_h, fp16* __restrict__ wku_l,
    const float* __restrict__ wo,  fp16* __restrict__ wo_h,  fp16* __restrict__ wo_l)
{
    __shared__ float tile[32][33];
    int z = blockIdx.x;
    const float* in; fp16 *oh, *ol;
    int R, Cc, bx;
    if (z < 1024)            { in = wq;  oh = wq_h;  ol = wq_l;  R = C_DIM; Cc = HD;       bx = 32; }
    else if (z < 1152)       { z -= 1024; in = wkd; oh = wkd_h; ol = wkd_l; R = C_DIM; Cc = RANK;   bx = 4;  }
    else if (z < 1408)       { z -= 1152; in = wku; oh = wku_h; ol = wku_l; R = RANK;  Cc = 2 * HD; bx = 64; }
    else                     { z -= 1408; in = wo;  oh = wo_h;  ol = wo_l;  R = HD;    Cc = C_DIM;  bx = 32; }
    int c0 = (z % bx) * 32;
    int r0 = (z / bx) * 32;
    int tx = threadIdx.x, ty = threadIdx.y;
    tile[ty][tx] = in[(size_t)(r0 + ty) * Cc + c0 + tx];
    __syncthreads();
    float v = tile[tx][ty];
    fp16 h, l; split_fp16(v, h, l);
    size_t o = (size_t)(c0 + ty) * R + r0 + tx;
    oh[o] = h; ol[o] = l;
}

// ---------------------------------------------------------------------------
// GEMM C[M,N] = A[M,K] @ B[N,K]^T, fp16 compensated, mma.sync.
// MODE==3: A hi/lo, B hi/lo, 3 MMAs (ah*bl + al*bh + ah*bh)  -> err ~2^-24
// MODE==2: A single,  B hi/lo, 2 MMAs (ah*bh + ah*bl)        -> err ~2^-12
// CTA 128x128, BK=16, 256 thr, 8 warps (4m x 2n), cp.async 4-stage + ldmatrix.
// smem stage regions (6144B each): 0=Ah 1=Al(MODE3) 2=Bh 3=Bl; rows 48B.
// ---------------------------------------------------------------------------
#define KPADB     48      // row stride bytes
#define REG_SZ    6144    // per-region bytes (128 rows * 48)
#define STG_SZ    24576   // stage bytes
#define NSTAGE    4
#define GEMM_SMEM (NSTAGE * STG_SZ)

struct FillPtrs { const fp16* p[4]; };

template <int MODE>
__device__ __forceinline__ void fill_stage(
    uint32_t sb, int stage, int kt, const FillPtrs& fp, int K, int tid)
{
    const int row  = tid >> 1;
    const int half = tid & 1;
    const uint32_t dbase = sb + stage * STG_SZ + row * KPADB + half * 16;
#pragma unroll
    for (int reg = 0; reg < 4; ++reg) {
        if (MODE == 2 && reg == 1) continue;
        const fp16* gp = fp.p[reg] + (size_t)row * K + kt + half * 8;
        cp16(dbase + reg * REG_SZ, gp);
    }
    cp_commit();
}

template <int MODE>
__global__ __launch_bounds__(256) void gemm_fp16_kernel(
    const fp16* __restrict__ Ah, const fp16* __restrict__ Al,
    const fp16* __restrict__ Bh, const fp16* __restrict__ Bl,
    float* __restrict__ Cf, fp16* __restrict__ Chi, fp16* __restrict__ Clo,
    int M, int N, int K)
{
    extern __shared__ char smem[];
    const uint32_t sb = smem_u32(smem);

    const int tid  = threadIdx.x;
    const int warp = tid >> 5;
    const int lid  = tid & 31;
    const int row0 = blockIdx.y * 128;
    const int col0 = blockIdx.x * 128;
    const int wm   = warp & 3;          // m-offset = wm*32
    const int wn   = warp >> 2;         // n-offset = wn*64
    const int g    = lid >> 2;
    const int tg   = lid & 3;
    const int m8   = lid >> 3;          // ldmatrix matrix index 0..3
    const int rl   = lid & 7;

    FillPtrs fp;
    fp.p[0] = Ah + (size_t)row0 * K;
    fp.p[1] = (MODE == 3 ? Al + (size_t)row0 * K : fp.p[0]);
    fp.p[2] = Bh + (size_t)col0 * K;
    fp.p[3] = Bl + (size_t)col0 * K;

    // ldmatrix per-lane base addresses (within stage 0)
    uint32_t a_addr[2][2];
#pragma unroll
    for (int mt = 0; mt < 2; ++mt)
#pragma unroll
        for (int hl = 0; hl < 2; ++hl) {
            int r = wm * 32 + mt * 16 + (m8 & 1) * 8 + rl;
            a_addr[mt][hl] = sb + hl * REG_SZ + r * KPADB + ((m8 >> 1) * 8) * 2;
        }
    uint32_t b_addr[4][2];
#pragma unroll
    for (int np = 0; np < 4; ++np)
#pragma unroll
        for (int hl = 0; hl < 2; ++hl) {
            int r = wn * 64 + np * 16 + (m8 >> 1) * 8 + rl;
            b_addr[np][hl] = sb + (2 + hl) * REG_SZ + r * KPADB + ((m8 & 1) * 8) * 2;
        }

    float acc[2][8][4];
#pragma unroll
    for (int mt = 0; mt < 2; ++mt)
#pragma unroll
        for (int nt = 0; nt < 8; ++nt)
#pragma unroll
            for (int r = 0; r < 4; ++r) acc[mt][nt][r] = 0.f;

    const int nk = K >> 4;

    // prologue: fill up to 3 stages
#pragma unroll
    for (int s = 0; s < NSTAGE - 1; ++s)
        if (s < nk) fill_stage<MODE>(sb, s, s << 4, fp, K, tid);

    for (int t = 0; t < nk; ++t) {
        if (t + 3 <= nk)      cp_wait<2>();
        else if (t + 2 == nk) cp_wait<1>();
        else                  cp_wait<0>();
        __syncthreads();

        const uint32_t soff = (uint32_t)(t & 3) * STG_SZ;

        uint32_t ah[2][4], al[2][4];
#pragma unroll
        for (int mt = 0; mt < 2; ++mt) {
            ldsm_x4(ah[mt][0], ah[mt][1], ah[mt][2], ah[mt][3], a_addr[mt][0] + soff);
            if (MODE == 3)
                ldsm_x4(al[mt][0], al[mt][1], al[mt][2], al[mt][3], a_addr[mt][1] + soff);
        }

#pragma unroll
        for (int np = 0; np < 4; ++np) {
            uint32_t bh[4], bl[4];
            ldsm_x4(bh[0], bh[1], bh[2], bh[3], b_addr[np][0] + soff);
            ldsm_x4(bl[0], bl[1], bl[2], bl[3], b_addr[np][1] + soff);
#pragma unroll
            for (int sub = 0; sub < 2; ++sub) {
                const int nt = np * 2 + sub;
#pragma unroll
                for (int mt = 0; mt < 2; ++mt) {
                    mma_fp16(acc[mt][nt], ah[mt][0], ah[mt][1], ah[mt][2], ah[mt][3],
                             bl[sub * 2], bl[sub * 2 + 1]);
                    if (MODE == 3)
                        mma_fp16(acc[mt][nt], al[mt][0], al[mt][1], al[mt][2], al[mt][3],
                                 bh[sub * 2], bh[sub * 2 + 1]);
                    mma_fp16(acc[mt][nt], ah[mt][0], ah[mt][1], ah[mt][2], ah[mt][3],
                             bh[sub * 2], bh[sub * 2 + 1]);
                }
            }
        }

        if (t + NSTAGE - 1 < nk)
            fill_stage<MODE>(sb, (t + 3) & 3, (t + 3) << 4, fp, K, tid);
    }

    // ---- epilogue ----
#pragma unroll
    for (int mt = 0; mt < 2; ++mt) {
#pragma unroll
        for (int nt = 0; nt < 8; ++nt) {
            const int r  = row0 + wm * 32 + mt * 16 + g;
            const int cc = col0 + wn * 64 + nt * 8 + 2 * tg;
            float* a = acc[mt][nt];
            if (Cf) {
                *(float2*)(Cf + (size_t)r * N + cc)       = make_float2(a[0], a[1]);
                *(float2*)(Cf + (size_t)(r + 8) * N + cc) = make_float2(a[2], a[3]);
            }
            if (Chi) {
                fp16 h0, l0, h1, l1;
                split_fp16(a[0], h0, l0); split_fp16(a[1], h1, l1);
                *(__half2*)(Chi + (size_t)r * N + cc) = __halves2half2(h0, h1);
                *(__half2*)(Clo + (size_t)r * N + cc) = __halves2half2(l0, l1);
                split_fp16(a[2], h0, l0); split_fp16(a[3], h1, l1);
                *(__half2*)(Chi + (size_t)(r + 8) * N + cc) = __halves2half2(h0, h1);
                *(__half2*)(Clo + (size_t)(r + 8) * N + cc) = __halves2half2(l0, l1);
            }
        }
    }
}

// ---------------------------------------------------------------------------
// Causal attention: one block per (b,h), one thread per query row (T=256).
// fp32 math; writes y as single fp16 (2-term out-GEMM covers the rounding).
// ---------------------------------------------------------------------------
__global__ __launch_bounds__(256) void attn_kernel(
    const float* __restrict__ qb, const float* __restrict__ kvb,
    fp16* __restrict__ yh)
{
    __shared__ float Ks[64][64];
    __shared__ float Vs[64][64];

    const int b = blockIdx.x >> 4;
    const int h = blockIdx.x & 15;
    const int i = threadIdx.x;

    const float* qrow = qb + ((size_t)(b * TT + i)) * HD + h * HS;
    float q[64];
#pragma unroll
    for (int d = 0; d < 64; ++d) q[d] = qrow[d];

    float m = -1e30f, l = 0.f;
    float acc[64];
#pragma unroll
    for (int d = 0; d < 64; ++d) acc[d] = 0.f;

    for (int c = 0; c < 4; ++c) {
        __syncthreads();
#pragma unroll
        for (int e = 0; e < 4; ++e) {
            int idx = threadIdx.x + e * 256;
            int r   = idx >> 4;
            int c4  = (idx & 15) << 2;
            const float* kvrow =
                kvb + ((size_t)(b * TT + c * 64 + r)) * (2 * HD) + h * HS;
            *(float4*)(&Ks[r][c4]) = *(const float4*)(kvrow + c4);
            *(float4*)(&Vs[r][c4]) = *(const float4*)(kvrow + HD + c4);
        }
        __syncthreads();

        int jmax = i - c * 64 + 1;
        if (jmax > 64) jmax = 64;
        for (int jj = 0; jj < jmax; ++jj) {
            float s = 0.f;
#pragma unroll
            for (int d4 = 0; d4 < 16; ++d4) {
                float4 k4 = *(const float4*)(&Ks[jj][d4 << 2]);
                s += q[d4 * 4 + 0] * k4.x + q[d4 * 4 + 1] * k4.y +
                     q[d4 * 4 + 2] * k4.z + q[d4 * 4 + 3] * k4.w;
            }
            s *= 0.125f;
            if (s > m) {
                float f = __expf(m - s);
                l *= f;
#pragma unroll
                for (int d = 0; d < 64; ++d) acc[d] *= f;
                m = s;
            }
            float p = __expf(s - m);
            l += p;
#pragma unroll
            for (int d4 = 0; d4 < 16; ++d4) {
                float4 v4 = *(const float4*)(&Vs[jj][d4 << 2]);
                acc[d4 * 4 + 0] += p * v4.x;
                acc[d4 * 4 + 1] += p * v4.y;
                acc[d4 * 4 + 2] += p * v4.z;
                acc[d4 * 4 + 3] += p * v4.w;
            }
        }
    }

    float inv = 1.0f / l;
    size_t yo = ((size_t)(b * TT + i)) * HD + h * HS;
#pragma unroll
    for (int d = 0; d < 64; d += 2) {
        __half2 p = __halves2half2(__float2half_rn(acc[d] * inv),
                                   __float2half_rn(acc[d + 1] * inv));
        *(__half2*)(yh + yo + d) = p;
    }
}

// ---------------------------------------------------------------------------
// kernel_launch — inputs: x, w_kv_down, w_kv_up, w_q, w_out (all fp32)
// ---------------------------------------------------------------------------
extern "C" void kernel_launch(void* const* d_in, const int* in_sizes, int n_in,
                              void* d_out, int out_size)
{
    const float* x         = (const float*)d_in[0];
    const float* w_kv_down = (const float*)d_in[1];
    const float* w_kv_up   = (const float*)d_in[2];
    const float* w_q       = (const float*)d_in[3];
    const float* w_out     = (const float*)d_in[4];
    float* out             = (float*)d_out;

    fp16 *x_hi, *x_lo, *wq_hi, *wq_lo, *wkvd_hi, *wkvd_lo;
    fp16 *wkvu_hi, *wkvu_lo, *wo_hi, *wo_lo;
    fp16 *lat_hi, *lat_lo, *y_h;
    float *q, *kv;
    cudaGetSymbolAddress((void**)&x_hi,   g_x_hi);
    cudaGetSymbolAddress((void**)&x_lo,   g_x_lo);
    cudaGetSymbolAddress((void**)&wq_hi,  g_wq_hi);
    cudaGetSymbolAddress((void**)&wq_lo,  g_wq_lo);
    cudaGetSymbolAddress((void**)&wkvd_hi,g_wkvd_hi);
    cudaGetSymbolAddress((void**)&wkvd_lo,g_wkvd_lo);
    cudaGetSymbolAddress((void**)&wkvu_hi,g_wkvu_hi);
    cudaGetSymbolAddress((void**)&wkvu_lo,g_wkvu_lo);
    cudaGetSymbolAddress((void**)&wo_hi,  g_wo_hi);
    cudaGetSymbolAddress((void**)&wo_lo,  g_wo_lo);
    cudaGetSymbolAddress((void**)&q,      g_q);
    cudaGetSymbolAddress((void**)&lat_hi, g_lat_hi);
    cudaGetSymbolAddress((void**)&lat_lo, g_lat_lo);
    cudaGetSymbolAddress((void**)&kv,     g_kv);
    cudaGetSymbolAddress((void**)&y_h,    g_y_h);

    cudaFuncSetAttribute(gemm_fp16_kernel<2>,
        cudaFuncAttributeMaxDynamicSharedMemorySize, GEMM_SMEM);
    cudaFuncSetAttribute(gemm_fp16_kernel<3>,
        cudaFuncAttributeMaxDynamicSharedMemorySize, GEMM_SMEM);

    // ---- prepass (2 launches) ----
    convert_kernel<<<(BT * C_DIM / 4 + 255) / 256, 256>>>(x, x_hi, x_lo, BT * C_DIM / 4);
    weights_kernel<<<2432, dim3(32, 32)>>>(
        w_q, wq_hi, wq_lo, w_kv_down, wkvd_hi, wkvd_lo,
        w_kv_up, wkvu_hi, wkvu_lo, w_out, wo_hi, wo_lo);

    dim3 blk(256);
    // q = x @ w_q (2-term: x_hi single, w hi/lo), fp32 out
    gemm_fp16_kernel<2><<<dim3(HD / 128, BT / 128), blk, GEMM_SMEM>>>(
        x_hi, nullptr, wq_hi, wq_lo, q, nullptr, nullptr, BT, HD, C_DIM);
    // latent = x @ w_kv_down (3-term), hi/lo out
    gemm_fp16_kernel<3><<<dim3(RANK / 128, BT / 128), blk, GEMM_SMEM>>>(
        x_hi, x_lo, wkvd_hi, wkvd_lo, nullptr, lat_hi, lat_lo, BT, RANK, C_DIM);
    // kv = latent @ w_kv_up (3-term), fp32 out
    gemm_fp16_kernel<3><<<dim3(2 * HD / 128, BT / 128), blk, GEMM_SMEM>>>(
        lat_hi, lat_lo, wkvu_hi, wkvu_lo, kv, nullptr, nullptr, BT, 2 * HD, RANK);
    // attention (writes y single fp16)
    attn_kernel<<<64 * NH, blk>>>(q, kv, y_h);
    // out = y @ w_out (2-term: y single, w hi/lo), fp32 out -> d_out
    gemm_fp16_kernel<2><<<dim3(C_DIM / 128, BT / 128), blk, GEMM_SMEM>>>(
        y_h, nullptr, wo_hi, wo_lo, out, nullptr, nullptr, BT, C_DIM, HD);
}